// round 2
// baseline (speedup 1.0000x reference)
#include <cuda_runtime.h>

// GRCell Kalman scan, T = 4,000,000 steps.
// x_{n+1} = M_n x_n + v_n * dy1_n   (affine; M_n/v_n from deterministic Riccati cov)
// Riccati contracts at e^(-271*dt)/step -> exact per-step params needed only for
// the first NPRE steps; afterwards a constant steady-state map applies.

#define T_TOTAL  4000000
#define NCHUNK   62500
#define LCH      64            // NCHUNK * LCH == T_TOTAL
#define LCH4     16            // LCH/4
#define NPRE     896           // steps of exact Riccati transient
#define NTRANS   14            // NPRE / LCH : transient chunks
#define DT_      1.0e-4f
#define GAMMA_   10.0f
#define SCAN_T   1024
#define GRP      62            // ceil(NCHUNK / SCAN_T)
#define K1_CB    1954          // ceil(NCHUNK/32)
#define K1_JB    2             // LCH/32
#define K4_BLK   64

__device__ float4 g_dyT4[NCHUNK * LCH4];  // [j4*NCHUNK + c] = dy1 steps 4j4..4j4+3 of chunk c
__device__ float4 g_cbuf[NPRE];           // per-step (m11, m21, v1, v2)
__device__ float4 g_steady[1];
__device__ float2 g_x0[1];
__device__ float4 g_aggP[NCHUNK];         // chunk map P: (p00,p01,p10,p11)
__device__ float2 g_aggQ[NCHUNK];         // chunk map q
__device__ float2 g_xstart[NCHUNK];       // state entering each chunk

// ---------------------------------------------------------------------------
// K1: transpose dy1 into g_dyT4  +  (one dedicated block) Riccati transient
// ---------------------------------------------------------------------------
__global__ void k1_transpose_riccati(const float* __restrict__ inp,
                                     const float* __restrict__ omega,
                                     const float* __restrict__ Cm,
                                     const float* __restrict__ Dm,
                                     const float* __restrict__ init)
{
    if (blockIdx.x == K1_CB * K1_JB) {
        if (threadIdx.x == 0 && threadIdx.y == 0) {
            const float om  = omega[0];
            const float c00 = Cm[0];                 // C = [[c00,0],[0,0]]
            const float d00 = Dm[0], d01 = Dm[1], d11 = Dm[3];
            const float c2  = c00 * c00;
            // minimal-chain constants
            const float nc2dt = -c2 * DT_;
            const float au    = 1.0f - GAMMA_ * DT_;  // coeff of u in linear part
            const float twomdt = 2.0f * om * DT_;
            const float omdt   = om * DT_;
            const float d00dt  = d00 * DT_;
            const float d01dt  = d01 * DT_;
            const float d11dt  = d11 * DT_;
            const float nwlin  = 1.0f - GAMMA_ * DT_;
            const float m200dt = -2.0f * om * DT_;    // hmm unused; keep explicit below
            (void)m200dt;
            float u = init[2], v = init[3], w = init[4];   // c11, c12, c22
            for (int n = 0; n < NPRE; n++) {
                // emit step-n map params (from pre-update cov)
                float m11 = 1.0f + DT_ * fmaf(-c2, u, -0.5f * GAMMA_);
                float m21 = DT_ * fmaf(-c2, v, -om);
                g_cbuf[n] = make_float4(m11, m21, c00 * u, c00 * v);
                // Riccati step, minimal dependent chains:
                // u' = u*(au - c2dt*u) + (2om*dt*v + d00dt)
                float tu = fmaf(nc2dt, u, au);            // shared with v'
                float su = fmaf(twomdt, v, d00dt);
                float sv = fmaf(omdt, w - u, d01dt);
                float tw = fmaf(nc2dt, v, -2.0f * om * DT_);
                float sw = fmaf(tw, v, d11dt);
                float un = fmaf(tu, u, su);
                float vn = fmaf(tu, v, sv);
                float wn = fmaf(nwlin, w, sw);
                u = un; v = vn; w = wn;
            }
            float m11 = 1.0f + DT_ * fmaf(-c2, u, -0.5f * GAMMA_);
            float m21 = DT_ * fmaf(-c2, v, -om);
            g_steady[0] = make_float4(m11, m21, c00 * u, c00 * v);
            g_x0[0] = make_float2(init[0], init[1]);
        }
        return;
    }

    __shared__ float tile[32][33];                     // tile[c_loc][j_loc]
    int bx = blockIdx.x % K1_CB;
    int by = blockIdx.x / K1_CB;
    int cb = bx * 32, jb = by * 32;

    #pragma unroll
    for (int k = threadIdx.y; k < 32; k += 8) {
        int c = cb + k;
        int j = jb + threadIdx.x;                      // always < LCH
        float vv = 0.0f;
        if (c < NCHUNK) vv = inp[(c * LCH + j) * 3 + 1];
        tile[k][threadIdx.x] = vv;
    }
    __syncthreads();
    // drain: each thread writes one float4 (4 consecutive j for one c)
    {
        int c_loc = threadIdx.x;
        int j4    = threadIdx.y;                       // 0..7
        int c = cb + c_loc;
        if (c < NCHUNK) {
            float4 vv = make_float4(tile[c_loc][4 * j4 + 0],
                                    tile[c_loc][4 * j4 + 1],
                                    tile[c_loc][4 * j4 + 2],
                                    tile[c_loc][4 * j4 + 3]);
            g_dyT4[((jb >> 2) + j4) * NCHUNK + c] = vv;
        }
    }
}

// ---------------------------------------------------------------------------
// K2: per-chunk affine map reduction
// ---------------------------------------------------------------------------
#define MAP_STEP(pr, dy)                                               \
    do {                                                               \
        float np00 = fmaf(pr.x, p00, m12 * p10);                       \
        float np10 = fmaf(pr.y, p00, m22 * p10);                       \
        float np01 = fmaf(pr.x, p01, m12 * p11);                       \
        float np11 = fmaf(pr.y, p01, m22 * p11);                       \
        float nq0  = fmaf(pr.x, q0, fmaf(m12, q1, pr.z * (dy)));       \
        float nq1  = fmaf(pr.y, q0, fmaf(m22, q1, pr.w * (dy)));       \
        p00 = np00; p10 = np10; p01 = np01; p11 = np11;                \
        q0 = nq0;  q1 = nq1;                                           \
    } while (0)

__global__ __launch_bounds__(128) void k2_chunk_maps(const float* __restrict__ omega)
{
    int c = blockIdx.x * 128 + threadIdx.x;
    if (c >= NCHUNK) return;
    const float m12 = DT_ * omega[0];
    const float m22 = 1.0f - 0.5f * GAMMA_ * DT_;
    float p00 = 1.f, p01 = 0.f, p10 = 0.f, p11 = 1.f, q0 = 0.f, q1 = 0.f;

    if (c < NTRANS) {                                  // transient chunk
        int nb = c * LCH;
        for (int j4 = 0; j4 < LCH4; j4++) {
            float4 d = g_dyT4[j4 * NCHUNK + c];
            float4 p0_ = g_cbuf[nb + 4 * j4 + 0]; MAP_STEP(p0_, d.x);
            float4 p1_ = g_cbuf[nb + 4 * j4 + 1]; MAP_STEP(p1_, d.y);
            float4 p2_ = g_cbuf[nb + 4 * j4 + 2]; MAP_STEP(p2_, d.z);
            float4 p3_ = g_cbuf[nb + 4 * j4 + 3]; MAP_STEP(p3_, d.w);
        }
    } else {                                           // steady chunk
        const float4 pr = g_steady[0];
        #pragma unroll
        for (int j4 = 0; j4 < LCH4; j4++) {
            float4 d = g_dyT4[j4 * NCHUNK + c];
            MAP_STEP(pr, d.x);
            MAP_STEP(pr, d.y);
            MAP_STEP(pr, d.z);
            MAP_STEP(pr, d.w);
        }
    }
    g_aggP[c] = make_float4(p00, p01, p10, p11);
    g_aggQ[c] = make_float2(q0, q1);
}

// ---------------------------------------------------------------------------
// K3: single-block scan over chunk maps -> chunk start states
// ---------------------------------------------------------------------------
__global__ __launch_bounds__(SCAN_T) void k3_scan()
{
    __shared__ float s0[SCAN_T], s1[SCAN_T], s2[SCAN_T],
                     s3[SCAN_T], s4[SCAN_T], s5[SCAN_T];
    int t = threadIdx.x;

    // group (GRP chunks) aggregate, composed left->right
    float a00 = 1.f, a01 = 0.f, a10 = 0.f, a11 = 1.f, aq0 = 0.f, aq1 = 0.f;
    for (int i = 0; i < GRP; i++) {
        int idx = t * GRP + i;
        if (idx < NCHUNK) {
            float4 P = g_aggP[idx];
            float2 Q = g_aggQ[idx];
            float n00 = P.x * a00 + P.y * a10;
            float n01 = P.x * a01 + P.y * a11;
            float n10 = P.z * a00 + P.w * a10;
            float n11 = P.z * a01 + P.w * a11;
            float nq0 = P.x * aq0 + P.y * aq1 + Q.x;
            float nq1 = P.z * aq0 + P.w * aq1 + Q.y;
            a00 = n00; a01 = n01; a10 = n10; a11 = n11; aq0 = nq0; aq1 = nq1;
        }
    }
    s0[t] = a00; s1[t] = a01; s2[t] = a10; s3[t] = a11; s4[t] = aq0; s5[t] = aq1;
    __syncthreads();

    // Hillis-Steele inclusive scan (operator: cur after prev)
    for (int d = 1; d < SCAN_T; d <<= 1) {
        float b00 = 0, b01 = 0, b10 = 0, b11 = 0, bq0 = 0, bq1 = 0;
        bool has = (t >= d);
        if (has) {
            b00 = s0[t - d]; b01 = s1[t - d]; b10 = s2[t - d];
            b11 = s3[t - d]; bq0 = s4[t - d]; bq1 = s5[t - d];
        }
        __syncthreads();
        if (has) {
            float n00 = a00 * b00 + a01 * b10;
            float n01 = a00 * b01 + a01 * b11;
            float n10 = a10 * b00 + a11 * b10;
            float n11 = a10 * b01 + a11 * b11;
            float nq0 = a00 * bq0 + a01 * bq1 + aq0;
            float nq1 = a10 * bq0 + a11 * bq1 + aq1;
            a00 = n00; a01 = n01; a10 = n10; a11 = n11; aq0 = nq0; aq1 = nq1;
            s0[t] = a00; s1[t] = a01; s2[t] = a10;
            s3[t] = a11; s4[t] = aq0; s5[t] = aq1;
        }
        __syncthreads();
    }

    // exclusive prefix for this group
    float e00 = 1.f, e01 = 0.f, e10 = 0.f, e11 = 1.f, eq0 = 0.f, eq1 = 0.f;
    if (t > 0) {
        e00 = s0[t - 1]; e01 = s1[t - 1]; e10 = s2[t - 1];
        e11 = s3[t - 1]; eq0 = s4[t - 1]; eq1 = s5[t - 1];
    }
    float x0a = g_x0[0].x, x0b = g_x0[0].y;
    float xs0 = e00 * x0a + e01 * x0b + eq0;
    float xs1 = e10 * x0a + e11 * x0b + eq1;
    for (int i = 0; i < GRP; i++) {
        int idx = t * GRP + i;
        if (idx < NCHUNK) {
            g_xstart[idx] = make_float2(xs0, xs1);
            float4 P = g_aggP[idx];
            float2 Q = g_aggQ[idx];
            float n0 = P.x * xs0 + P.y * xs1 + Q.x;
            float n1 = P.z * xs0 + P.w * xs1 + Q.y;
            xs0 = n0; xs1 = n1;
        }
    }
}

// ---------------------------------------------------------------------------
// K4: replay each chunk, emit outputs via smem staging (coalesced stores)
// ---------------------------------------------------------------------------
__global__ __launch_bounds__(K4_BLK) void k4_emit(const float* __restrict__ omega,
                                                  float* __restrict__ out)
{
    __shared__ float smf[K4_BLK * 132];     // 132 = 2*LCH + 4 pad (keeps f4 align)
    int c = blockIdx.x * K4_BLK + threadIdx.x;
    bool active = (c < NCHUNK);
    const float m12 = DT_ * omega[0];
    const float m22 = 1.0f - 0.5f * GAMMA_ * DT_;
    const float4 sp = g_steady[0];
    bool trans = active && (c < NTRANS);
    float x0_ = 0.f, x1_ = 0.f;
    if (active) { float2 xs = g_xstart[c]; x0_ = xs.x; x1_ = xs.y; }
    int c0 = blockIdx.x * K4_BLK;

    if (active) {
        float* row = &smf[threadIdx.x * 132];
        #define EMIT_STEP(pr, dy, jj)                                          \
            do {                                                               \
                float nx0 = fmaf((pr).x, x0_, fmaf(m12, x1_, (pr).z * (dy))); \
                float nx1 = fmaf((pr).y, x0_, fmaf(m22, x1_, (pr).w * (dy))); \
                x0_ = nx0; x1_ = nx1;                                          \
                row[2 * (jj)    ] = nx0;                                       \
                row[2 * (jj) + 1] = nx1;                                       \
            } while (0)
        if (trans) {
            int nb = c * LCH;
            for (int j4 = 0; j4 < LCH4; j4++) {
                float4 d = g_dyT4[j4 * NCHUNK + c];
                float4 q0_ = g_cbuf[nb + 4 * j4 + 0]; EMIT_STEP(q0_, d.x, 4 * j4 + 0);
                float4 q1_ = g_cbuf[nb + 4 * j4 + 1]; EMIT_STEP(q1_, d.y, 4 * j4 + 1);
                float4 q2_ = g_cbuf[nb + 4 * j4 + 2]; EMIT_STEP(q2_, d.z, 4 * j4 + 2);
                float4 q3_ = g_cbuf[nb + 4 * j4 + 3]; EMIT_STEP(q3_, d.w, 4 * j4 + 3);
            }
        } else {
            #pragma unroll
            for (int j4 = 0; j4 < LCH4; j4++) {
                float4 d = g_dyT4[j4 * NCHUNK + c];
                EMIT_STEP(sp, d.x, 4 * j4 + 0);
                EMIT_STEP(sp, d.y, 4 * j4 + 1);
                EMIT_STEP(sp, d.z, 4 * j4 + 2);
                EMIT_STEP(sp, d.w, 4 * j4 + 3);
            }
        }
        #undef EMIT_STEP
    }
    __syncthreads();
    // 64 chunks x 32 float4 -> coalesced stores (512B per warp-instr)
    for (int idx = threadIdx.x; idx < K4_BLK * 32; idx += K4_BLK) {
        int s  = idx >> 5;
        int q4 = idx & 31;
        int cc = c0 + s;
        if (cc < NCHUNK) {
            float4 vv = *reinterpret_cast<float4*>(&smf[s * 132 + q4 * 4]);
            *reinterpret_cast<float4*>(&out[cc * (2 * LCH) + q4 * 4]) = vv;
        }
    }
}

// ---------------------------------------------------------------------------
extern "C" void kernel_launch(void* const* d_in, const int* in_sizes, int n_in,
                              void* d_out, int out_size)
{
    const float* inp   = (const float*)d_in[0];   // (T,3)
    const float* omega = (const float*)d_in[1];   // (1,1)
    const float* Cm    = (const float*)d_in[2];   // (2,2)
    const float* Dm    = (const float*)d_in[3];   // (2,2)
    const float* init  = (const float*)d_in[4];   // (5,)
    float* out = (float*)d_out;                   // (T,2)

    dim3 b1(32, 8);
    k1_transpose_riccati<<<K1_CB * K1_JB + 1, b1>>>(inp, omega, Cm, Dm, init);
    k2_chunk_maps<<<(NCHUNK + 127) / 128, 128>>>(omega);
    k3_scan<<<1, SCAN_T>>>();
    k4_emit<<<(NCHUNK + K4_BLK - 1) / K4_BLK, K4_BLK>>>(omega, out);
}

// round 3
// speedup vs baseline: 3.1163x; 3.1163x over previous
#include <cuda_runtime.h>

// GRCell Kalman scan, T = 4,000,000 steps.
// x_{n+1} = M_n x_n + v_n * dy1_n   (affine; M_n/v_n from deterministic Riccati cov)
// Riccati contracts at ~e^(-0.022/step) -> exact per-step params needed only for
// the first NPRE steps; afterwards a constant steady-state map applies.

#define T_TOTAL  4000000
#define NCHUNK   62500
#define LCH      64            // NCHUNK * LCH == T_TOTAL
#define LCH4     16            // LCH/4
#define NPRE     640           // steps of exact Riccati transient
#define NTRANS   10            // NPRE / LCH : transient chunks
#define DT_      1.0e-4f
#define GAMMA_   10.0f
#define K1_CB    1954          // ceil(NCHUNK/32)
#define K1_JB    2             // LCH/32
#define BLK2_T   1024
#define NBLK2    62            // ceil(NCHUNK / 1024)
#define NPREF    (NBLK2 * BLK2_T)
#define K4_BLK   128
#define K4_TJ    16            // staging tile (steps)

__device__ float4 g_dyT4[NCHUNK * LCH4];  // [j4*NCHUNK + c] = dy1 steps 4j4..4j4+3 of chunk c
__device__ float4 g_cbuf[NPRE];           // per-step (m11, m21, v1, v2)
__device__ float4 g_steady[1];
__device__ float2 g_x0[1];
__device__ float4 g_prefP[NPREF];         // in-block inclusive prefix map P
__device__ float2 g_prefQ[NPREF];         // in-block inclusive prefix map q
__device__ float4 g_baggP[NBLK2];         // block aggregate P
__device__ float2 g_baggQ[NBLK2];         // block aggregate q
__device__ float2 g_xb[NBLK2];            // state entering each 1024-chunk block

// ---------------------------------------------------------------------------
// K1: transpose dy1 into g_dyT4  +  (one dedicated block) Riccati transient
// ---------------------------------------------------------------------------
__global__ void k1_transpose_riccati(const float* __restrict__ inp,
                                     const float* __restrict__ omega,
                                     const float* __restrict__ Cm,
                                     const float* __restrict__ Dm,
                                     const float* __restrict__ init)
{
    __shared__ float  tile[32][33];                    // transpose tile
    __shared__ float4 ring[128];                       // riccati store ring

    if (blockIdx.x == K1_CB * K1_JB) {
        if (threadIdx.y != 0) return;                  // one warp only
        int lane = threadIdx.x;
        const float om  = omega[0];
        const float c00 = Cm[0];                       // C = [[c00,0],[0,0]]
        const float d00 = Dm[0], d01 = Dm[1], d11 = Dm[3];
        const float c2  = c00 * c00;
        const float nc2dt  = -c2 * DT_;
        const float au     = 1.0f - GAMMA_ * DT_;
        const float twomdt = 2.0f * om * DT_;
        const float omdt   = om * DT_;
        const float d00dt  = d00 * DT_;
        const float d01dt  = d01 * DT_;
        const float d11dt  = d11 * DT_;
        const float mhalf  = -0.5f * GAMMA_;
        const float n2omdt = -2.0f * om * DT_;
        float u = init[2], v = init[3], w = init[4];   // c11, c12, c22

        for (int base = 0; base < NPRE; base += 128) {
            if (lane == 0) {
                #pragma unroll 4
                for (int i = 0; i < 128; i++) {
                    float m11 = 1.0f + DT_ * fmaf(-c2, u, mhalf);
                    float m21 = DT_ * fmaf(-c2, v, -om);
                    ring[i] = make_float4(m11, m21, c00 * u, c00 * v);
                    float tu = fmaf(nc2dt, u, au);
                    float su = fmaf(twomdt, v, d00dt);
                    float sv = fmaf(omdt, w - u, d01dt);
                    float tw = fmaf(nc2dt, v, n2omdt);
                    float sw = fmaf(tw, v, d11dt);
                    float un = fmaf(tu, u, su);
                    float vn = fmaf(tu, v, sv);
                    float wn = fmaf(au, w, sw);
                    u = un; v = vn; w = wn;
                }
            }
            __syncwarp();
            #pragma unroll
            for (int i = lane; i < 128; i += 32)
                g_cbuf[base + i] = ring[i];
            __syncwarp();
        }
        if (lane == 0) {
            float m11 = 1.0f + DT_ * fmaf(-c2, u, mhalf);
            float m21 = DT_ * fmaf(-c2, v, -om);
            g_steady[0] = make_float4(m11, m21, c00 * u, c00 * v);
            g_x0[0] = make_float2(init[0], init[1]);
        }
        return;
    }

    int bx = blockIdx.x % K1_CB;
    int by = blockIdx.x / K1_CB;
    int cb = bx * 32, jb = by * 32;

    #pragma unroll
    for (int k = threadIdx.y; k < 32; k += 8) {
        int c = cb + k;
        int j = jb + threadIdx.x;                      // always < LCH
        float vv = 0.0f;
        if (c < NCHUNK) vv = inp[(c * LCH + j) * 3 + 1];
        tile[k][threadIdx.x] = vv;
    }
    __syncthreads();
    // drain: each thread writes one float4 (4 consecutive j for one c)
    {
        int c_loc = threadIdx.x;
        int j4l   = threadIdx.y;                       // 0..7
        int c = cb + c_loc;
        if (c < NCHUNK) {
            float4 vv = make_float4(tile[c_loc][4 * j4l + 0],
                                    tile[c_loc][4 * j4l + 1],
                                    tile[c_loc][4 * j4l + 2],
                                    tile[c_loc][4 * j4l + 3]);
            g_dyT4[((jb >> 2) + j4l) * NCHUNK + c] = vv;
        }
    }
}

// ---------------------------------------------------------------------------
// K2: per-chunk affine map + in-block Hillis-Steele scan (fused)
// ---------------------------------------------------------------------------
#define MAP_STEP(pr, dy)                                               \
    do {                                                               \
        float np00 = fmaf(pr.x, p00, m12 * p10);                       \
        float np10 = fmaf(pr.y, p00, m22 * p10);                       \
        float np01 = fmaf(pr.x, p01, m12 * p11);                       \
        float np11 = fmaf(pr.y, p01, m22 * p11);                       \
        float nq0  = fmaf(pr.x, q0, fmaf(m12, q1, pr.z * (dy)));       \
        float nq1  = fmaf(pr.y, q0, fmaf(m22, q1, pr.w * (dy)));       \
        p00 = np00; p10 = np10; p01 = np01; p11 = np11;                \
        q0 = nq0;  q1 = nq1;                                           \
    } while (0)

__global__ __launch_bounds__(BLK2_T) void k2_maps_scan(const float* __restrict__ omega)
{
    __shared__ float s0[BLK2_T], s1[BLK2_T], s2[BLK2_T],
                     s3[BLK2_T], s4[BLK2_T], s5[BLK2_T];
    int t = threadIdx.x;
    int c = blockIdx.x * BLK2_T + t;
    const float m12 = DT_ * omega[0];
    const float m22 = 1.0f - 0.5f * GAMMA_ * DT_;
    float p00 = 1.f, p01 = 0.f, p10 = 0.f, p11 = 1.f, q0 = 0.f, q1 = 0.f;

    if (c < NCHUNK) {
        if (c < NTRANS) {                              // transient chunk
            int nb = c * LCH;
            for (int j4 = 0; j4 < LCH4; j4++) {
                float4 d = g_dyT4[j4 * NCHUNK + c];
                float4 pa = g_cbuf[nb + 4 * j4 + 0]; MAP_STEP(pa, d.x);
                float4 pb = g_cbuf[nb + 4 * j4 + 1]; MAP_STEP(pb, d.y);
                float4 pc = g_cbuf[nb + 4 * j4 + 2]; MAP_STEP(pc, d.z);
                float4 pd = g_cbuf[nb + 4 * j4 + 3]; MAP_STEP(pd, d.w);
            }
        } else {                                       // steady chunk
            const float4 pr = g_steady[0];
            #pragma unroll 4
            for (int j4 = 0; j4 < LCH4; j4++) {
                float4 d = g_dyT4[j4 * NCHUNK + c];
                MAP_STEP(pr, d.x);
                MAP_STEP(pr, d.y);
                MAP_STEP(pr, d.z);
                MAP_STEP(pr, d.w);
            }
        }
    }

    float a00 = p00, a01 = p01, a10 = p10, a11 = p11, aq0 = q0, aq1 = q1;
    s0[t] = a00; s1[t] = a01; s2[t] = a10; s3[t] = a11; s4[t] = aq0; s5[t] = aq1;
    __syncthreads();

    // Hillis-Steele inclusive scan (operator: cur after prev)
    #pragma unroll
    for (int d = 1; d < BLK2_T; d <<= 1) {
        float b00 = 0, b01 = 0, b10 = 0, b11 = 0, bq0 = 0, bq1 = 0;
        bool has = (t >= d);
        if (has) {
            b00 = s0[t - d]; b01 = s1[t - d]; b10 = s2[t - d];
            b11 = s3[t - d]; bq0 = s4[t - d]; bq1 = s5[t - d];
        }
        __syncthreads();
        if (has) {
            float n00 = a00 * b00 + a01 * b10;
            float n01 = a00 * b01 + a01 * b11;
            float n10 = a10 * b00 + a11 * b10;
            float n11 = a10 * b01 + a11 * b11;
            float nq0 = a00 * bq0 + a01 * bq1 + aq0;
            float nq1 = a10 * bq0 + a11 * bq1 + aq1;
            a00 = n00; a01 = n01; a10 = n10; a11 = n11; aq0 = nq0; aq1 = nq1;
            s0[t] = a00; s1[t] = a01; s2[t] = a10;
            s3[t] = a11; s4[t] = aq0; s5[t] = aq1;
        }
        __syncthreads();
    }

    int gi = blockIdx.x * BLK2_T + t;
    g_prefP[gi] = make_float4(a00, a01, a10, a11);
    g_prefQ[gi] = make_float2(aq0, aq1);
    if (t == BLK2_T - 1) {
        g_baggP[blockIdx.x] = make_float4(a00, a01, a10, a11);
        g_baggQ[blockIdx.x] = make_float2(aq0, aq1);
    }
}

// ---------------------------------------------------------------------------
// K3: tiny serial pass over 62 block aggregates -> block start states
// ---------------------------------------------------------------------------
__global__ void k3_blockstarts()
{
    if (threadIdx.x != 0) return;
    float x0_ = g_x0[0].x, x1_ = g_x0[0].y;
    for (int b = 0; b < NBLK2; b++) {
        g_xb[b] = make_float2(x0_, x1_);
        float4 P = g_baggP[b];
        float2 Q = g_baggQ[b];
        float n0 = P.x * x0_ + P.y * x1_ + Q.x;
        float n1 = P.z * x0_ + P.w * x1_ + Q.y;
        x0_ = n0; x1_ = n1;
    }
}

// ---------------------------------------------------------------------------
// K4: replay each chunk, emit outputs via smem staging (coalesced stores)
// ---------------------------------------------------------------------------
__global__ __launch_bounds__(K4_BLK, 6) void k4_emit(const float* __restrict__ omega,
                                                     float* __restrict__ out)
{
    __shared__ float smf[K4_BLK * 33];      // rows of 2*K4_TJ+1 (stride 33: conflict-free)
    int c = blockIdx.x * K4_BLK + threadIdx.x;
    bool active = (c < NCHUNK);
    const float m12 = DT_ * omega[0];
    const float m22 = 1.0f - 0.5f * GAMMA_ * DT_;
    const float4 sp = g_steady[0];
    bool trans = active && (c < NTRANS);
    int c0 = blockIdx.x * K4_BLK;

    float x0_ = 0.f, x1_ = 0.f;
    if (active) {
        int b = c >> 10;
        int tl = c & 1023;
        float2 xb = g_xb[b];
        if (tl == 0) { x0_ = xb.x; x1_ = xb.y; }
        else {
            float4 P = g_prefP[c - 1];
            float2 Q = g_prefQ[c - 1];
            x0_ = P.x * xb.x + P.y * xb.y + Q.x;
            x1_ = P.z * xb.x + P.w * xb.y + Q.y;
        }
    }

    float* row = &smf[threadIdx.x * 33];
    #define EMIT_STEP(pr, dy, jj)                                          \
        do {                                                               \
            float nx0 = fmaf((pr).x, x0_, fmaf(m12, x1_, (pr).z * (dy))); \
            float nx1 = fmaf((pr).y, x0_, fmaf(m22, x1_, (pr).w * (dy))); \
            x0_ = nx0; x1_ = nx1;                                          \
            row[2 * (jj)    ] = nx0;                                       \
            row[2 * (jj) + 1] = nx1;                                       \
        } while (0)

    #pragma unroll
    for (int tb = 0; tb < LCH / K4_TJ; tb++) {
        if (active) {
            int j4base = tb * (K4_TJ / 4);
            if (trans) {
                int nb = c * LCH + tb * K4_TJ;
                for (int j4 = 0; j4 < K4_TJ / 4; j4++) {
                    float4 d = g_dyT4[(j4base + j4) * NCHUNK + c];
                    float4 qa = g_cbuf[nb + 4 * j4 + 0]; EMIT_STEP(qa, d.x, 4 * j4 + 0);
                    float4 qb = g_cbuf[nb + 4 * j4 + 1]; EMIT_STEP(qb, d.y, 4 * j4 + 1);
                    float4 qc = g_cbuf[nb + 4 * j4 + 2]; EMIT_STEP(qc, d.z, 4 * j4 + 2);
                    float4 qd = g_cbuf[nb + 4 * j4 + 3]; EMIT_STEP(qd, d.w, 4 * j4 + 3);
                }
            } else {
                #pragma unroll
                for (int j4 = 0; j4 < K4_TJ / 4; j4++) {
                    float4 d = g_dyT4[(j4base + j4) * NCHUNK + c];
                    EMIT_STEP(sp, d.x, 4 * j4 + 0);
                    EMIT_STEP(sp, d.y, 4 * j4 + 1);
                    EMIT_STEP(sp, d.z, 4 * j4 + 2);
                    EMIT_STEP(sp, d.w, 4 * j4 + 3);
                }
            }
        }
        __syncthreads();
        // drain: K4_BLK chunks x 8 float4 (scalar smem loads, conflict-free)
        #pragma unroll
        for (int i = 0; i < 8; i++) {
            int idx = threadIdx.x + i * K4_BLK;
            int s   = idx >> 3;
            int q4  = idx & 7;
            int cc  = c0 + s;
            if (cc < NCHUNK) {
                const float* src = &smf[s * 33 + q4 * 4];
                float4 vv = make_float4(src[0], src[1], src[2], src[3]);
                *reinterpret_cast<float4*>(&out[cc * (2 * LCH) + tb * (2 * K4_TJ) + q4 * 4]) = vv;
            }
        }
        __syncthreads();
    }
    #undef EMIT_STEP
}

// ---------------------------------------------------------------------------
extern "C" void kernel_launch(void* const* d_in, const int* in_sizes, int n_in,
                              void* d_out, int out_size)
{
    const float* inp   = (const float*)d_in[0];   // (T,3)
    const float* omega = (const float*)d_in[1];   // (1,1)
    const float* Cm    = (const float*)d_in[2];   // (2,2)
    const float* Dm    = (const float*)d_in[3];   // (2,2)
    const float* init  = (const float*)d_in[4];   // (5,)
    float* out = (float*)d_out;                   // (T,2)

    dim3 b1(32, 8);
    k1_transpose_riccati<<<K1_CB * K1_JB + 1, b1>>>(inp, omega, Cm, Dm, init);
    k2_maps_scan<<<NBLK2, BLK2_T>>>(omega);
    k3_blockstarts<<<1, 32>>>();
    k4_emit<<<(NCHUNK + K4_BLK - 1) / K4_BLK, K4_BLK>>>(omega, out);
}